// round 3
// baseline (speedup 1.0000x reference)
#include <cuda_runtime.h>
#include <cuda_bf16.h>

#define H 8
#define FIN 128
#define HID 128
#define FOUT 64
#define LDA 136          // padded smem stride (elems): 272B rows -> ldmatrix conflict-free
#define NMAX 131072
#define NTMAX (NMAX / 128)
#define NCH 16

// Scratch (static device globals; no runtime allocation)
__device__ float g_h[(size_t)NMAX * H * HID];         // intermediate h [N,H,HID]
__device__ float g_psum[(size_t)H * NTMAX * HID];     // per-tile column sums
__device__ float g_psumsq[(size_t)H * NTMAX * HID];
__device__ float g_ps2[H * NCH * HID];
__device__ float g_pq2[H * NCH * HID];
__device__ float g_scale[H * HID];
__device__ float g_shift[H * HID];

// Pre-split weights, already in smem layout [n][k] with LDA stride
__device__ __nv_bfloat16 g_w1hi[H * 128 * LDA];
__device__ __nv_bfloat16 g_w1lo[H * 128 * LDA];
__device__ __nv_bfloat16 g_w2hi[H * 64 * LDA];
__device__ __nv_bfloat16 g_w2lo[H * 64 * LDA];

__device__ __forceinline__ void bsplit(float f, __nv_bfloat16 &hi, __nv_bfloat16 &lo) {
    hi = __float2bfloat16(f);
    lo = __float2bfloat16(f - __bfloat162float(hi));
}

__device__ __forceinline__ unsigned packbf2(__nv_bfloat16 a, __nv_bfloat16 b) {
    __nv_bfloat162 t; t.x = a; t.y = b;
    return *reinterpret_cast<unsigned *>(&t);
}

// 8-byte packed store of 4 bf16
__device__ __forceinline__ void st_bf4(__nv_bfloat16 *p, __nv_bfloat16 a, __nv_bfloat16 b,
                                       __nv_bfloat16 c, __nv_bfloat16 d) {
    uint2 t; t.x = packbf2(a, b); t.y = packbf2(c, d);
    *reinterpret_cast<uint2 *>(p) = t;
}

__device__ __forceinline__ void cpasync16(unsigned saddr, const void *gaddr) {
    asm volatile("cp.async.ca.shared.global [%0], [%1], 16;\n" :: "r"(saddr), "l"(gaddr));
}
__device__ __forceinline__ void cpasync_commit() { asm volatile("cp.async.commit_group;\n"); }
__device__ __forceinline__ void cpasync_wait0()  { asm volatile("cp.async.wait_group 0;\n"); }

__device__ __forceinline__ void ldsm4(unsigned &r0, unsigned &r1, unsigned &r2, unsigned &r3,
                                      unsigned addr) {
    asm volatile("ldmatrix.sync.aligned.m8n8.x4.shared.b16 {%0,%1,%2,%3}, [%4];\n"
                 : "=r"(r0), "=r"(r1), "=r"(r2), "=r"(r3) : "r"(addr));
}

__device__ __forceinline__ void mma16816(float c[4], const unsigned a[4],
                                         unsigned b0, unsigned b1) {
    asm volatile(
        "mma.sync.aligned.m16n8k16.row.col.f32.bf16.bf16.f32 "
        "{%0,%1,%2,%3}, {%4,%5,%6,%7}, {%8,%9}, {%0,%1,%2,%3};\n"
        : "+f"(c[0]), "+f"(c[1]), "+f"(c[2]), "+f"(c[3])
        : "r"(a[0]), "r"(a[1]), "r"(a[2]), "r"(a[3]), "r"(b0), "r"(b1));
}

// ---------------------------------------------------------------------------
// K0: pre-split weights into bf16 hi/lo, transposed to [n][k]*LDA layout.
// One block per head.
// ---------------------------------------------------------------------------
__global__ void k_prep(const float *__restrict__ w1, const float *__restrict__ w2)
{
    const int hd = blockIdx.x;
    const int tid = threadIdx.x;
    const float *w1h = w1 + (size_t)hd * FIN * HID;
    __nv_bfloat16 *o1h = g_w1hi + (size_t)hd * 128 * LDA;
    __nv_bfloat16 *o1l = g_w1lo + (size_t)hd * 128 * LDA;
    for (int i = tid; i < 128 * 128; i += blockDim.x) {
        int n = i & 127, k = i >> 7;
        float f = w1h[(size_t)k * HID + n];
        __nv_bfloat16 hi, lo; bsplit(f, hi, lo);
        o1h[n * LDA + k] = hi; o1l[n * LDA + k] = lo;
    }
    const float *w2h = w2 + (size_t)hd * HID * FOUT;
    __nv_bfloat16 *o2h = g_w2hi + (size_t)hd * 64 * LDA;
    __nv_bfloat16 *o2l = g_w2lo + (size_t)hd * 64 * LDA;
    for (int i = tid; i < 64 * 128; i += blockDim.x) {
        int n = i & 63, k = i >> 6;
        float f = w2h[(size_t)k * FOUT + n];
        __nv_bfloat16 hi, lo; bsplit(f, hi, lo);
        o2h[n * LDA + k] = hi; o2l[n * LDA + k] = lo;
    }
}

// ---------------------------------------------------------------------------
// K1: h = x @ w1 + b1 (per head), 3-pass bf16-split MMA, fp32 accum.
// 1024 threads, block tile 128x128, warp grid 4m x 8n (warp tile 32x16).
// B tiles cp.async'd from pre-split weights; writes h + per-tile stats.
// ---------------------------------------------------------------------------
__global__ void __launch_bounds__(1024, 1)
k_gemm1(const float *__restrict__ x, const float *__restrict__ b1, int N, int NT)
{
    extern __shared__ unsigned char smraw[];
    __nv_bfloat16 *Ahi = (__nv_bfloat16 *)smraw;
    __nv_bfloat16 *Alo = Ahi + 128 * LDA;
    __nv_bfloat16 *Bhi = Alo + 128 * LDA;
    __nv_bfloat16 *Blo = Bhi + 128 * LDA;
    float *psS = (float *)(Blo + 128 * LDA);   // [4][HID]
    float *pqS = psS + 4 * HID;                // [4][HID]

    const int tid = threadIdx.x;
    const int hd = blockIdx.y;
    const int n0 = blockIdx.x * 128;

    // ---- kick off B fill via cp.async (pre-split, already in layout) ----
    {
        unsigned sBhi = (unsigned)__cvta_generic_to_shared(Bhi);
        unsigned sBlo = (unsigned)__cvta_generic_to_shared(Blo);
        const __nv_bfloat16 *srcHi = g_w1hi + (size_t)hd * 128 * LDA;
        const __nv_bfloat16 *srcLo = g_w1lo + (size_t)hd * 128 * LDA;
        const int NCHK = 128 * LDA / 8;        // 16B chunks per split
        for (int i = tid; i < NCHK; i += 1024) {
            cpasync16(sBhi + i * 16, srcHi + i * 8);
            cpasync16(sBlo + i * 16, srcLo + i * 8);
        }
        cpasync_commit();
    }

    // ---- fill A (x tile), split into hi/lo bf16 ----
    #pragma unroll
    for (int i = tid; i < 128 * 32; i += 1024) {
        int r = i >> 5, c4 = (i & 31) << 2;
        float4 v = make_float4(0.f, 0.f, 0.f, 0.f);
        int row = n0 + r;
        if (row < N)
            v = *reinterpret_cast<const float4 *>(x + ((size_t)row * H + hd) * FIN + c4);
        __nv_bfloat16 h0, h1, h2, h3, l0, l1, l2, l3;
        bsplit(v.x, h0, l0); bsplit(v.y, h1, l1);
        bsplit(v.z, h2, l2); bsplit(v.w, h3, l3);
        st_bf4(Ahi + r * LDA + c4, h0, h1, h2, h3);
        st_bf4(Alo + r * LDA + c4, l0, l1, l2, l3);
    }
    cpasync_wait0();
    __syncthreads();

    const int lane = tid & 31;
    const int w = tid >> 5;
    const int gid = lane >> 2, tig = lane & 3;
    const int wm = w & 3, wn = w >> 2;     // 4 m-warps x 8 n-warps; warp tile 32x16

    const int lr = lane & 15;
    const int kh = ((lane >> 4) & 1) << 3;
    unsigned sAhi = (unsigned)__cvta_generic_to_shared(Ahi);
    unsigned sAlo = (unsigned)__cvta_generic_to_shared(Alo);
    unsigned sBhi = (unsigned)__cvta_generic_to_shared(Bhi);
    unsigned sBlo = (unsigned)__cvta_generic_to_shared(Blo);
    unsigned aHiAd[2], aLoAd[2], bHiAd, bLoAd;
    #pragma unroll
    for (int mf = 0; mf < 2; mf++) {
        unsigned off = ((wm * 32 + mf * 16 + lr) * LDA + kh) * 2;
        aHiAd[mf] = sAhi + off; aLoAd[mf] = sAlo + off;
    }
    {
        unsigned off = ((wn * 16 + lr) * LDA + kh) * 2;
        bHiAd = sBhi + off; bLoAd = sBlo + off;
    }

    float acc[2][2][4];
    #pragma unroll
    for (int mf = 0; mf < 2; mf++)
        #pragma unroll
        for (int nf = 0; nf < 2; nf++)
            #pragma unroll
            for (int q = 0; q < 4; q++) acc[mf][nf][q] = 0.f;

    #pragma unroll
    for (int kc = 0; kc < 8; kc++) {
        const unsigned kadv = kc * 32;
        unsigned ah[2][4], al[2][4], bh[4], bl[4];
        #pragma unroll
        for (int mf = 0; mf < 2; mf++) {
            ldsm4(ah[mf][0], ah[mf][1], ah[mf][2], ah[mf][3], aHiAd[mf] + kadv);
            ldsm4(al[mf][0], al[mf][1], al[mf][2], al[mf][3], aLoAd[mf] + kadv);
        }
        ldsm4(bh[0], bh[1], bh[2], bh[3], bHiAd + kadv);
        ldsm4(bl[0], bl[1], bl[2], bl[3], bLoAd + kadv);
        #pragma unroll
        for (int mf = 0; mf < 2; mf++) {
            mma16816(acc[mf][0], ah[mf], bh[0], bh[2]);
            mma16816(acc[mf][0], ah[mf], bl[0], bl[2]);
            mma16816(acc[mf][0], al[mf], bh[0], bh[2]);
            mma16816(acc[mf][1], ah[mf], bh[1], bh[3]);
            mma16816(acc[mf][1], ah[mf], bl[1], bl[3]);
            mma16816(acc[mf][1], al[mf], bh[1], bh[3]);
        }
    }

    // ---- epilogue: +b1, store h, per-column stats ----
    const float *b1h = b1 + hd * HID;
    #pragma unroll
    for (int nf = 0; nf < 2; nf++) {
        const int col = wn * 16 + nf * 8 + tig * 2;
        const float be = b1h[col], bo = b1h[col + 1];
        float se = 0.f, qe = 0.f, so = 0.f, qo = 0.f;
        #pragma unroll
        for (int mf = 0; mf < 2; mf++) {
            const int r0 = n0 + wm * 32 + mf * 16 + gid;
            const int r1 = r0 + 8;
            float v0 = acc[mf][nf][0] + be;
            float v1 = acc[mf][nf][1] + bo;
            float v2 = acc[mf][nf][2] + be;
            float v3 = acc[mf][nf][3] + bo;
            if (r0 < N) {
                float2 t; t.x = v0; t.y = v1;
                *reinterpret_cast<float2 *>(g_h + ((size_t)r0 * H + hd) * HID + col) = t;
                se += v0; qe += v0 * v0; so += v1; qo += v1 * v1;
            }
            if (r1 < N) {
                float2 t; t.x = v2; t.y = v3;
                *reinterpret_cast<float2 *>(g_h + ((size_t)r1 * H + hd) * HID + col) = t;
                se += v2; qe += v2 * v2; so += v3; qo += v3 * v3;
            }
        }
        #pragma unroll
        for (int off = 16; off >= 4; off >>= 1) {
            se += __shfl_xor_sync(0xffffffffu, se, off);
            so += __shfl_xor_sync(0xffffffffu, so, off);
            qe += __shfl_xor_sync(0xffffffffu, qe, off);
            qo += __shfl_xor_sync(0xffffffffu, qo, off);
        }
        if (gid == 0) {
            psS[wm * HID + col] = se; psS[wm * HID + col + 1] = so;
            pqS[wm * HID + col] = qe; pqS[wm * HID + col + 1] = qo;
        }
    }
    __syncthreads();
    if (tid < HID) {
        float s = psS[tid] + psS[HID + tid] + psS[2 * HID + tid] + psS[3 * HID + tid];
        float q = pqS[tid] + pqS[HID + tid] + pqS[2 * HID + tid] + pqS[3 * HID + tid];
        size_t o = ((size_t)hd * NT + blockIdx.x) * HID + tid;
        g_psum[o] = s; g_psumsq[o] = q;
    }
}

// ---------------------------------------------------------------------------
// K2a/K2b: deterministic fixed-order reduction of tile stats -> BN scale/shift
// ---------------------------------------------------------------------------
__global__ void k_stats_a(int NT)
{
    const int hd = blockIdx.x, ch = blockIdx.y, c = threadIdx.x;
    const int per = (NT + NCH - 1) / NCH;
    int t0 = ch * per;
    int t1 = min(NT, t0 + per);
    const float *ps = g_psum + (size_t)hd * NT * HID + c;
    const float *pq = g_psumsq + (size_t)hd * NT * HID + c;
    float s0 = 0, s1 = 0, s2 = 0, s3 = 0, q0 = 0, q1 = 0, q2 = 0, q3 = 0;
    int t = t0;
    for (; t + 4 <= t1; t += 4) {
        s0 += ps[(size_t)(t + 0) * HID]; q0 += pq[(size_t)(t + 0) * HID];
        s1 += ps[(size_t)(t + 1) * HID]; q1 += pq[(size_t)(t + 1) * HID];
        s2 += ps[(size_t)(t + 2) * HID]; q2 += pq[(size_t)(t + 2) * HID];
        s3 += ps[(size_t)(t + 3) * HID]; q3 += pq[(size_t)(t + 3) * HID];
    }
    for (; t < t1; t++) { s0 += ps[(size_t)t * HID]; q0 += pq[(size_t)t * HID]; }
    g_ps2[(hd * NCH + ch) * HID + c] = (s0 + s1) + (s2 + s3);
    g_pq2[(hd * NCH + ch) * HID + c] = (q0 + q1) + (q2 + q3);
}

__global__ void k_stats_b(const float *__restrict__ bn_w, const float *__restrict__ bn_b, int N)
{
    const int hd = blockIdx.x, c = threadIdx.x;
    float s = 0.f, q = 0.f;
    #pragma unroll
    for (int ch = 0; ch < NCH; ch++) {
        s += g_ps2[(hd * NCH + ch) * HID + c];
        q += g_pq2[(hd * NCH + ch) * HID + c];
    }
    float invN = 1.0f / (float)N;
    float mean = s * invN;
    float var = fmaxf(q * invN - mean * mean, 0.f);
    float inv = rsqrtf(var + 1e-5f);
    float sc = bn_w[hd * HID + c] * inv;
    g_scale[hd * HID + c] = sc;
    g_shift[hd * HID + c] = bn_b[hd * HID + c] - mean * sc;
}

// ---------------------------------------------------------------------------
// K3: y = relu(h*scale + shift) @ w2 + b2, 3-pass bf16-split MMA.
// 512 threads, block tile 128x64, warp grid 4x4 (warp tile 32x16).
// ---------------------------------------------------------------------------
__global__ void __launch_bounds__(512, 2)
k_gemm2(const float *__restrict__ b2, float *__restrict__ out, int N)
{
    extern __shared__ unsigned char smraw[];
    __nv_bfloat16 *Ahi = (__nv_bfloat16 *)smraw;
    __nv_bfloat16 *Alo = Ahi + 128 * LDA;
    __nv_bfloat16 *Bhi = Alo + 128 * LDA;
    __nv_bfloat16 *Blo = Bhi + 64 * LDA;
    float *scS = (float *)(Blo + 64 * LDA);
    float *shS = scS + HID;

    const int tid = threadIdx.x;
    const int hd = blockIdx.y;
    const int n0 = blockIdx.x * 128;

    // ---- kick off B fill via cp.async ----
    {
        unsigned sBhi = (unsigned)__cvta_generic_to_shared(Bhi);
        unsigned sBlo = (unsigned)__cvta_generic_to_shared(Blo);
        const __nv_bfloat16 *srcHi = g_w2hi + (size_t)hd * 64 * LDA;
        const __nv_bfloat16 *srcLo = g_w2lo + (size_t)hd * 64 * LDA;
        const int NCHK = 64 * LDA / 8;
        for (int i = tid; i < NCHK; i += 512) {
            cpasync16(sBhi + i * 16, srcHi + i * 8);
            cpasync16(sBlo + i * 16, srcLo + i * 8);
        }
        cpasync_commit();
    }

    if (tid < HID) {
        scS[tid] = g_scale[hd * HID + tid];
        shS[tid] = g_shift[hd * HID + tid];
    }
    __syncthreads();

    // ---- fill A = relu(h*s + t), split hi/lo ----
    #pragma unroll
    for (int i = tid; i < 128 * 32; i += 512) {
        int r = i >> 5, c4 = (i & 31) << 2;
        int row = n0 + r;
        float4 v = make_float4(0.f, 0.f, 0.f, 0.f);
        if (row < N)
            v = *reinterpret_cast<const float4 *>(g_h + ((size_t)row * H + hd) * HID + c4);
        float4 sc = *reinterpret_cast<const float4 *>(scS + c4);
        float4 sh = *reinterpret_cast<const float4 *>(shS + c4);
        float a0 = fmaxf(v.x * sc.x + sh.x, 0.f);
        float a1 = fmaxf(v.y * sc.y + sh.y, 0.f);
        float a2 = fmaxf(v.z * sc.z + sh.z, 0.f);
        float a3 = fmaxf(v.w * sc.w + sh.w, 0.f);
        if (row >= N) { a0 = a1 = a2 = a3 = 0.f; }
        __nv_bfloat16 h0, h1, h2, h3, l0, l1, l2, l3;
        bsplit(a0, h0, l0); bsplit(a1, h1, l1);
        bsplit(a2, h2, l2); bsplit(a3, h3, l3);
        st_bf4(Ahi + r * LDA + c4, h0, h1, h2, h3);
        st_bf4(Alo + r * LDA + c4, l0, l1, l2, l3);
    }
    cpasync_wait0();
    __syncthreads();

    const int lane = tid & 31;
    const int w = tid >> 5;
    const int gid = lane >> 2, tig = lane & 3;
    const int wm = w & 3, wn = w >> 2;     // warp tile: rows wm*32.., cols wn*16..

    const int lr = lane & 15;
    const int kh = ((lane >> 4) & 1) << 3;
    unsigned sAhi = (unsigned)__cvta_generic_to_shared(Ahi);
    unsigned sAlo = (unsigned)__cvta_generic_to_shared(Alo);
    unsigned sBhi = (unsigned)__cvta_generic_to_shared(Bhi);
    unsigned sBlo = (unsigned)__cvta_generic_to_shared(Blo);
    unsigned aHiAd[2], aLoAd[2], bHiAd, bLoAd;
    #pragma unroll
    for (int mf = 0; mf < 2; mf++) {
        unsigned off = ((wm * 32 + mf * 16 + lr) * LDA + kh) * 2;
        aHiAd[mf] = sAhi + off; aLoAd[mf] = sAlo + off;
    }
    {
        unsigned off = ((wn * 16 + lr) * LDA + kh) * 2;
        bHiAd = sBhi + off; bLoAd = sBlo + off;
    }

    float acc[2][2][4];
    #pragma unroll
    for (int mf = 0; mf < 2; mf++)
        #pragma unroll
        for (int nf = 0; nf < 2; nf++)
            #pragma unroll
            for (int q = 0; q < 4; q++) acc[mf][nf][q] = 0.f;

    #pragma unroll
    for (int kc = 0; kc < 8; kc++) {
        const unsigned kadv = kc * 32;
        unsigned ah[2][4], al[2][4], bh[4], bl[4];
        #pragma unroll
        for (int mf = 0; mf < 2; mf++) {
            ldsm4(ah[mf][0], ah[mf][1], ah[mf][2], ah[mf][3], aHiAd[mf] + kadv);
            ldsm4(al[mf][0], al[mf][1], al[mf][2], al[mf][3], aLoAd[mf] + kadv);
        }
        ldsm4(bh[0], bh[1], bh[2], bh[3], bHiAd + kadv);
        ldsm4(bl[0], bl[1], bl[2], bl[3], bLoAd + kadv);
        #pragma unroll
        for (int mf = 0; mf < 2; mf++) {
            mma16816(acc[mf][0], ah[mf], bh[0], bh[2]);
            mma16816(acc[mf][0], ah[mf], bl[0], bl[2]);
            mma16816(acc[mf][0], al[mf], bh[0], bh[2]);
            mma16816(acc[mf][1], ah[mf], bh[1], bh[3]);
            mma16816(acc[mf][1], ah[mf], bl[1], bl[3]);
            mma16816(acc[mf][1], al[mf], bh[1], bh[3]);
        }
    }

    // ---- epilogue: +b2, store y ----
    const float *b2h = b2 + hd * FOUT;
    #pragma unroll
    for (int nf = 0; nf < 2; nf++) {
        const int col = wn * 16 + nf * 8 + tig * 2;
        const float be = b2h[col], bo = b2h[col + 1];
        #pragma unroll
        for (int mf = 0; mf < 2; mf++) {
            const int r0 = n0 + wm * 32 + mf * 16 + gid;
            const int r1 = r0 + 8;
            if (r0 < N) {
                float2 t; t.x = acc[mf][nf][0] + be; t.y = acc[mf][nf][1] + bo;
                *reinterpret_cast<float2 *>(out + ((size_t)r0 * H + hd) * FOUT + col) = t;
            }
            if (r1 < N) {
                float2 t; t.x = acc[mf][nf][2] + be; t.y = acc[mf][nf][3] + bo;
                *reinterpret_cast<float2 *>(out + ((size_t)r1 * H + hd) * FOUT + col) = t;
            }
        }
    }
}

// ---------------------------------------------------------------------------
extern "C" void kernel_launch(void *const *d_in, const int *in_sizes, int n_in,
                              void *d_out, int out_size)
{
    (void)n_in; (void)out_size;
    const float *x    = (const float *)d_in[0];
    const float *w1   = (const float *)d_in[1];
    const float *b1   = (const float *)d_in[2];
    const float *bn_w = (const float *)d_in[3];
    const float *bn_b = (const float *)d_in[4];
    const float *w2   = (const float *)d_in[5];
    const float *b2   = (const float *)d_in[6];
    float *out = (float *)d_out;

    const int N = in_sizes[0] / (H * FIN);
    const int NT = (N + 127) / 128;

    const int SM1 = 4 * 128 * LDA * 2 + 2 * 4 * HID * 4;               // 143360 B
    const int SM3 = (2 * 128 * LDA + 2 * 64 * LDA) * 2 + 2 * HID * 4;  // 105472 B

    cudaFuncSetAttribute(k_gemm1, cudaFuncAttributeMaxDynamicSharedMemorySize, SM1);
    cudaFuncSetAttribute(k_gemm2, cudaFuncAttributeMaxDynamicSharedMemorySize, SM3);

    k_prep<<<H, 512>>>(w1, w2);
    k_gemm1<<<dim3(NT, H), 1024, SM1>>>(x, b1, N, NT);
    k_stats_a<<<dim3(H, NCH), HID>>>(NT);
    k_stats_b<<<H, HID>>>(bn_w, bn_b, N);
    k_gemm2<<<dim3(NT, H), 512, SM3>>>(b2, out, N);
}

// round 8
// speedup vs baseline: 1.0112x; 1.0112x over previous
// GroupMLP — round 6 resubmission of round-4 design (two prior container-level
// infra failures; source re-audited, no kernel-side fault candidate found).
// K1/K3 both: 128x64 block tile, 512 thr, 4x4 warps, ~106KB smem, 2 CTAs/SM.
#include <cuda_runtime.h>
#include <cuda_bf16.h>

#define H 8
#define FIN 128
#define HID 128
#define FOUT 64
#define LDA 136          // padded smem stride (elems): 272B rows -> ldmatrix conflict-free
#define NMAX 131072
#define NTMAX (NMAX / 128)
#define NCH 16

// Scratch (static device globals; no runtime allocation)
__device__ float g_h[(size_t)NMAX * H * HID];         // intermediate h [N,H,HID]
__device__ float g_psum[(size_t)H * NTMAX * HID];     // per-tile column sums
__device__ float g_psumsq[(size_t)H * NTMAX * HID];
__device__ float g_ps2[H * NCH * HID];
__device__ float g_pq2[H * NCH * HID];
__device__ float g_scale[H * HID];
__device__ float g_shift[H * HID];

// Pre-split weights, already in smem layout [n][k] with LDA stride
__device__ __nv_bfloat16 g_w1hi[H * 128 * LDA];
__device__ __nv_bfloat16 g_w1lo[H * 128 * LDA];
__device__ __nv_bfloat16 g_w2hi[H * 64 * LDA];
__device__ __nv_bfloat16 g_w2lo[H * 64 * LDA];

__device__ __forceinline__ void bsplit(float f, __nv_bfloat16 &hi, __nv_bfloat16 &lo) {
    hi = __float2bfloat16(f);
    lo = __float2bfloat16(f - __bfloat162float(hi));
}

__device__ __forceinline__ unsigned packbf2(__nv_bfloat16 a, __nv_bfloat16 b) {
    __nv_bfloat162 t; t.x = a; t.y = b;
    return *reinterpret_cast<unsigned *>(&t);
}

// 8-byte packed store of 4 bf16
__device__ __forceinline__ void st_bf4(__nv_bfloat16 *p, __nv_bfloat16 a, __nv_bfloat16 b,
                                       __nv_bfloat16 c, __nv_bfloat16 d) {
    uint2 t; t.x = packbf2(a, b); t.y = packbf2(c, d);
    *reinterpret_cast<uint2 *>(p) = t;
}

__device__ __forceinline__ void cpasync16(unsigned saddr, const void *gaddr) {
    asm volatile("cp.async.ca.shared.global [%0], [%1], 16;\n" :: "r"(saddr), "l"(gaddr));
}
__device__ __forceinline__ void cpasync_commit() { asm volatile("cp.async.commit_group;\n"); }
__device__ __forceinline__ void cpasync_wait0()  { asm volatile("cp.async.wait_group 0;\n"); }

__device__ __forceinline__ void ldsm4(unsigned &r0, unsigned &r1, unsigned &r2, unsigned &r3,
                                      unsigned addr) {
    asm volatile("ldmatrix.sync.aligned.m8n8.x4.shared.b16 {%0,%1,%2,%3}, [%4];\n"
                 : "=r"(r0), "=r"(r1), "=r"(r2), "=r"(r3) : "r"(addr));
}

__device__ __forceinline__ void mma16816(float c[4], const unsigned a[4],
                                         unsigned b0, unsigned b1) {
    asm volatile(
        "mma.sync.aligned.m16n8k16.row.col.f32.bf16.bf16.f32 "
        "{%0,%1,%2,%3}, {%4,%5,%6,%7}, {%8,%9}, {%0,%1,%2,%3};\n"
        : "+f"(c[0]), "+f"(c[1]), "+f"(c[2]), "+f"(c[3])
        : "r"(a[0]), "r"(a[1]), "r"(a[2]), "r"(a[3]), "r"(b0), "r"(b1));
}

// ---------------------------------------------------------------------------
// K0: pre-split weights into bf16 hi/lo, transposed to [n][k]*LDA layout.
// ---------------------------------------------------------------------------
__global__ void k_prep(const float *__restrict__ w1, const float *__restrict__ w2)
{
    const int hd = blockIdx.x;
    const int tid = threadIdx.x;
    const float *w1h = w1 + (size_t)hd * FIN * HID;
    __nv_bfloat16 *o1h = g_w1hi + (size_t)hd * 128 * LDA;
    __nv_bfloat16 *o1l = g_w1lo + (size_t)hd * 128 * LDA;
    for (int i = tid; i < 128 * 128; i += blockDim.x) {
        int n = i & 127, k = i >> 7;
        float f = w1h[(size_t)k * HID + n];
        __nv_bfloat16 hi, lo; bsplit(f, hi, lo);
        o1h[n * LDA + k] = hi; o1l[n * LDA + k] = lo;
    }
    const float *w2h = w2 + (size_t)hd * HID * FOUT;
    __nv_bfloat16 *o2h = g_w2hi + (size_t)hd * 64 * LDA;
    __nv_bfloat16 *o2l = g_w2lo + (size_t)hd * 64 * LDA;
    for (int i = tid; i < 64 * 128; i += blockDim.x) {
        int n = i & 63, k = i >> 6;
        float f = w2h[(size_t)k * FOUT + n];
        __nv_bfloat16 hi, lo; bsplit(f, hi, lo);
        o2h[n * LDA + k] = hi; o2l[n * LDA + k] = lo;
    }
}

// ---------------------------------------------------------------------------
// K1: h = x @ w1 + b1 (per head), 3-pass bf16-split MMA, fp32 accum.
// 512 threads, block tile 128x64 (HID split in 2 col-blocks), warp grid 4x4
// (warp tile 32x16), smem ~106KB -> 2 CTAs/SM. Writes h + per-tile stats.
// ---------------------------------------------------------------------------
__global__ void __launch_bounds__(512, 2)
k_gemm1(const float *__restrict__ x, const float *__restrict__ b1, int N, int NT)
{
    extern __shared__ unsigned char smraw[];
    __nv_bfloat16 *Ahi = (__nv_bfloat16 *)smraw;
    __nv_bfloat16 *Alo = Ahi + 128 * LDA;
    __nv_bfloat16 *Bhi = Alo + 128 * LDA;
    __nv_bfloat16 *Blo = Bhi + 64 * LDA;
    float *psS = (float *)(Blo + 64 * LDA);    // [4][64]
    float *pqS = psS + 4 * 64;                 // [4][64]

    const int tid = threadIdx.x;
    const int hd = blockIdx.y >> 1;
    const int c0 = (blockIdx.y & 1) * 64;      // column half of HID
    const int n0 = blockIdx.x * 128;

    // ---- kick off B fill via cp.async (pre-split, already in layout) ----
    {
        unsigned sBhi = (unsigned)__cvta_generic_to_shared(Bhi);
        unsigned sBlo = (unsigned)__cvta_generic_to_shared(Blo);
        const __nv_bfloat16 *srcHi = g_w1hi + ((size_t)hd * 128 + c0) * LDA;
        const __nv_bfloat16 *srcLo = g_w1lo + ((size_t)hd * 128 + c0) * LDA;
        const int NCHK = 64 * LDA / 8;         // 16B chunks per split
        for (int i = tid; i < NCHK; i += 512) {
            cpasync16(sBhi + i * 16, srcHi + i * 8);
            cpasync16(sBlo + i * 16, srcLo + i * 8);
        }
        cpasync_commit();
    }

    // ---- fill A (x tile), split into hi/lo bf16 ----
    #pragma unroll
    for (int i = tid; i < 128 * 32; i += 512) {
        int r = i >> 5, c4 = (i & 31) << 2;
        float4 v = make_float4(0.f, 0.f, 0.f, 0.f);
        int row = n0 + r;
        if (row < N)
            v = *reinterpret_cast<const float4 *>(x + ((size_t)row * H + hd) * FIN + c4);
        __nv_bfloat16 h0, h1, h2, h3, l0, l1, l2, l3;
        bsplit(v.x, h0, l0); bsplit(v.y, h1, l1);
        bsplit(v.z, h2, l2); bsplit(v.w, h3, l3);
        st_bf4(Ahi + r * LDA + c4, h0, h1, h2, h3);
        st_bf4(Alo + r * LDA + c4, l0, l1, l2, l3);
    }
    cpasync_wait0();
    __syncthreads();

    const int lane = tid & 31;
    const int w = tid >> 5;
    const int gid = lane >> 2, tig = lane & 3;
    const int wm = w & 3, wn = w >> 2;     // warp tile: rows wm*32.., cols wn*16..

    const int lr = lane & 15;
    const int kh = ((lane >> 4) & 1) << 3;
    unsigned sAhi = (unsigned)__cvta_generic_to_shared(Ahi);
    unsigned sAlo = (unsigned)__cvta_generic_to_shared(Alo);
    unsigned sBhi = (unsigned)__cvta_generic_to_shared(Bhi);
    unsigned sBlo = (unsigned)__cvta_generic_to_shared(Blo);
    unsigned aHiAd[2], aLoAd[2], bHiAd, bLoAd;
    #pragma unroll
    for (int mf = 0; mf < 2; mf++) {
        unsigned off = ((wm * 32 + mf * 16 + lr) * LDA + kh) * 2;
        aHiAd[mf] = sAhi + off; aLoAd[mf] = sAlo + off;
    }
    {
        unsigned off = ((wn * 16 + lr) * LDA + kh) * 2;
        bHiAd = sBhi + off; bLoAd = sBlo + off;
    }

    float acc[2][2][4];
    #pragma unroll
    for (int mf = 0; mf < 2; mf++)
        #pragma unroll
        for (int nf = 0; nf < 2; nf++)
            #pragma unroll
            for (int q = 0; q < 4; q++) acc[mf][nf][q] = 0.f;

    #pragma unroll
    for (int kc = 0; kc < 8; kc++) {
        const unsigned kadv = kc * 32;
        unsigned ah[2][4], al[2][4], bh[4], bl[4];
        #pragma unroll
        for (int mf = 0; mf < 2; mf++) {
            ldsm4(ah[mf][0], ah[mf][1], ah[mf][2], ah[mf][3], aHiAd[mf] + kadv);
            ldsm4(al[mf][0], al[mf][1], al[mf][2], al[mf][3], aLoAd[mf] + kadv);
        }
        ldsm4(bh[0], bh[1], bh[2], bh[3], bHiAd + kadv);
        ldsm4(bl[0], bl[1], bl[2], bl[3], bLoAd + kadv);
        #pragma unroll
        for (int mf = 0; mf < 2; mf++) {
            mma16816(acc[mf][0], ah[mf], bh[0], bh[2]);
            mma16816(acc[mf][0], ah[mf], bl[0], bl[2]);
            mma16816(acc[mf][0], al[mf], bh[0], bh[2]);
            mma16816(acc[mf][1], ah[mf], bh[1], bh[3]);
            mma16816(acc[mf][1], ah[mf], bl[1], bl[3]);
            mma16816(acc[mf][1], al[mf], bh[1], bh[3]);
        }
    }

    // ---- epilogue: +b1, store h, per-column stats ----
    const float *b1h = b1 + hd * HID;
    #pragma unroll
    for (int nf = 0; nf < 2; nf++) {
        const int lcol = wn * 16 + nf * 8 + tig * 2;   // local col in [0,64)
        const int col = c0 + lcol;                     // global col in HID
        const float be = b1h[col], bo = b1h[col + 1];
        float se = 0.f, qe = 0.f, so = 0.f, qo = 0.f;
        #pragma unroll
        for (int mf = 0; mf < 2; mf++) {
            const int r0 = n0 + wm * 32 + mf * 16 + gid;
            const int r1 = r0 + 8;
            float v0 = acc[mf][nf][0] + be;
            float v1 = acc[mf][nf][1] + bo;
            float v2 = acc[mf][nf][2] + be;
            float v3 = acc[mf][nf][3] + bo;
            if (r0 < N) {
                float2 t; t.x = v0; t.y = v1;
                *reinterpret_cast<float2 *>(g_h + ((size_t)r0 * H + hd) * HID + col) = t;
                se += v0; qe += v0 * v0; so += v1; qo += v1 * v1;
            }
            if (r1 < N) {
                float2 t; t.x = v2; t.y = v3;
                *reinterpret_cast<float2 *>(g_h + ((size_t)r1 * H + hd) * HID + col) = t;
                se += v2; qe += v2 * v2; so += v3; qo += v3 * v3;
            }
        }
        #pragma unroll
        for (int off = 16; off >= 4; off >>= 1) {
            se += __shfl_xor_sync(0xffffffffu, se, off);
            so += __shfl_xor_sync(0xffffffffu, so, off);
            qe += __shfl_xor_sync(0xffffffffu, qe, off);
            qo += __shfl_xor_sync(0xffffffffu, qo, off);
        }
        if (gid == 0) {
            psS[wm * 64 + lcol] = se; psS[wm * 64 + lcol + 1] = so;
            pqS[wm * 64 + lcol] = qe; pqS[wm * 64 + lcol + 1] = qo;
        }
    }
    __syncthreads();
    if (tid < 64) {
        float s = psS[tid] + psS[64 + tid] + psS[128 + tid] + psS[192 + tid];
        float q = pqS[tid] + pqS[64 + tid] + pqS[128 + tid] + pqS[192 + tid];
        size_t o = ((size_t)hd * NT + blockIdx.x) * HID + c0 + tid;
        g_psum[o] = s; g_psumsq[o] = q;
    }
}

// ---------------------------------------------------------------------------
// K2a/K2b: deterministic fixed-order reduction of tile stats -> BN scale/shift
// ---------------------------------------------------------------------------
__global__ void k_stats_a(int NT)
{
    const int hd = blockIdx.x, ch = blockIdx.y, c = threadIdx.x;
    const int per = (NT + NCH - 1) / NCH;
    int t0 = ch * per;
    int t1 = min(NT, t0 + per);
    const float *ps = g_psum + (size_t)hd * NT * HID + c;
    const float *pq = g_psumsq + (size_t)hd * NT * HID + c;
    float s0 = 0, s1 = 0, s2 = 0, s3 = 0, q0 = 0, q1 = 0, q2 = 0, q3 = 0;
    int t = t0;
    for (; t + 4 <= t1; t += 4) {
        s0 += ps[(size_t)(t + 0) * HID]; q0 += pq[(size_t)(t + 0) * HID];
        s1 += ps[(size_t)(t + 1) * HID]; q1 += pq[(size_t)(t + 1) * HID];
        s2 += ps[(size_t)(t + 2) * HID]; q2 += pq[(size_t)(t + 2) * HID];
        s3 += ps[(size_t)(t + 3) * HID]; q3 += pq[(size_t)(t + 3) * HID];
    }
    for (; t < t1; t++) { s0 += ps[(size_t)t * HID]; q0 += pq[(size_t)t * HID]; }
    g_ps2[(hd * NCH + ch) * HID + c] = (s0 + s1) + (s2 + s3);
    g_pq2[(hd * NCH + ch) * HID + c] = (q0 + q1) + (q2 + q3);
}

__global__ void k_stats_b(const float *__restrict__ bn_w, const float *__restrict__ bn_b, int N)
{
    const int hd = blockIdx.x, c = threadIdx.x;
    float s = 0.f, q = 0.f;
    #pragma unroll
    for (int ch = 0; ch < NCH; ch++) {
        s += g_ps2[(hd * NCH + ch) * HID + c];
        q += g_pq2[(hd * NCH + ch) * HID + c];
    }
    float invN = 1.0f / (float)N;
    float mean = s * invN;
    float var = fmaxf(q * invN - mean * mean, 0.f);
    float inv = rsqrtf(var + 1e-5f);
    float sc = bn_w[hd * HID + c] * inv;
    g_scale[hd * HID + c] = sc;
    g_shift[hd * HID + c] = bn_b[hd * HID + c] - mean * sc;
}

// ---------------------------------------------------------------------------
// K3: y = relu(h*scale + shift) @ w2 + b2, 3-pass bf16-split MMA.
// 512 threads, block tile 128x64, warp grid 4x4 (warp tile 32x16), 2 CTAs/SM.
// ---------------------------------------------------------------------------
__global__ void __launch_bounds__(512, 2)
k_gemm2(const float *__restrict__ b2, float *__restrict__ out, int N)
{
    extern __shared__ unsigned char smraw[];
    __nv_bfloat16 *Ahi = (__nv_bfloat16 *)smraw;
    __nv_bfloat16 *Alo = Ahi + 128 * LDA;
    __nv_bfloat16 *Bhi = Alo + 128 * LDA;
    __nv_bfloat16 *Blo = Bhi + 64 * LDA;
    float *scS = (float *)(Blo + 64 * LDA);
    float *shS = scS + HID;

    const int tid = threadIdx.x;
    const int hd = blockIdx.y;
    const int n0 = blockIdx.x * 128;

    // ---- kick off B fill via cp.async ----
    {
        unsigned sBhi = (unsigned)__cvta_generic_to_shared(Bhi);
        unsigned sBlo = (unsigned)__cvta_generic_to_shared(Blo);
        const __nv_bfloat16 *srcHi = g_w2hi + (size_t)hd * 64 * LDA;
        const __nv_bfloat16 *srcLo = g_w2lo + (size_t)hd * 64 * LDA;
        const int NCHK = 64 * LDA / 8;
        for (int i = tid; i < NCHK; i += 512) {
            cpasync16(sBhi + i * 16, srcHi + i * 8);
            cpasync16(sBlo + i * 16, srcLo + i * 8);
        }
        cpasync_commit();
    }

    if (tid < HID) {
        scS[tid] = g_scale[hd * HID + tid];
        shS[tid] = g_shift[hd * HID + tid];
    }
    __syncthreads();

    // ---- fill A = relu(h*s + t), split hi/lo ----
    #pragma unroll
    for (int i = tid; i < 128 * 32; i += 512) {
        int r = i >> 5, c4 = (i & 31) << 2;
        int row = n0 + r;
        float4 v = make_float4(0.f, 0.f, 0.f, 0.f);
        if (row < N)
            v = *reinterpret_cast<const float4 *>(g_h + ((size_t)row * H + hd) * HID + c4);
        float4 sc = *reinterpret_cast<const float4 *>(scS + c4);
        float4 sh = *reinterpret_cast<const float4 *>(shS + c4);
        float a0 = fmaxf(v.x * sc.x + sh.x, 0.f);
        float a1 = fmaxf(v.y * sc.y + sh.y, 0.f);
        float a2 = fmaxf(v.z * sc.z + sh.z, 0.f);
        float a3 = fmaxf(v.w * sc.w + sh.w, 0.f);
        if (row >= N) { a0 = a1 = a2 = a3 = 0.f; }
        __nv_bfloat16 h0, h1, h2, h3, l0, l1, l2, l3;
        bsplit(a0, h0, l0); bsplit(a1, h1, l1);
        bsplit(a2, h2, l2); bsplit(a3, h3, l3);
        st_bf4(Ahi + r * LDA + c4, h0, h1, h2, h3);
        st_bf4(Alo + r * LDA + c4, l0, l1, l2, l3);
    }
    cpasync_wait0();
    __syncthreads();

    const int lane = tid & 31;
    const int w = tid >> 5;
    const int gid = lane >> 2, tig = lane & 3;
    const int wm = w & 3, wn = w >> 2;     // warp tile: rows wm*32.., cols wn*16..

    const int lr = lane & 15;
    const int kh = ((lane >> 4) & 1) << 3;
    unsigned sAhi = (unsigned)__cvta_generic_to_shared(Ahi);
    unsigned sAlo = (unsigned)__cvta_generic_to_shared(Alo);
    unsigned sBhi = (unsigned)__cvta_generic_to_shared(Bhi);
    unsigned sBlo = (unsigned)__cvta_generic_to_shared(Blo);
    unsigned aHiAd[2], aLoAd[2], bHiAd, bLoAd;
    #pragma unroll
    for (int mf = 0; mf < 2; mf++) {
        unsigned off = ((wm * 32 + mf * 16 + lr) * LDA + kh) * 2;
        aHiAd[mf] = sAhi + off; aLoAd[mf] = sAlo + off;
    }
    {
        unsigned off = ((wn * 16 + lr) * LDA + kh) * 2;
        bHiAd = sBhi + off; bLoAd = sBlo + off;
    }

    float acc[2][2][4];
    #pragma unroll
    for (int mf = 0; mf < 2; mf++)
        #pragma unroll
        for (int nf = 0; nf < 2; nf++)
            #pragma unroll
            for (int q = 0; q < 4; q++) acc[mf][nf][q] = 0.f;

    #pragma unroll
    for (int kc = 0; kc < 8; kc++) {
        const unsigned kadv = kc * 32;
        unsigned ah[2][4], al[2][4], bh[4], bl[4];
        #pragma unroll
        for (int mf = 0; mf < 2; mf++) {
            ldsm4(ah[mf][0], ah[mf][1], ah[mf][2], ah[mf][3], aHiAd[mf] + kadv);
            ldsm4(al[mf][0], al[mf][1], al[mf][2], al[mf][3], aLoAd[mf] + kadv);
        }
        ldsm4(bh[0], bh[1], bh[2], bh[3], bHiAd + kadv);
        ldsm4(bl[0], bl[1], bl[2], bl[3], bLoAd + kadv);
        #pragma unroll
        for (int mf = 0; mf < 2; mf++) {
            mma16816(acc[mf][0], ah[mf], bh[0], bh[2]);
            mma16816(acc[mf][0], ah[mf], bl[0], bl[2]);
            mma16816(acc[mf][0], al[mf], bh[0], bh[2]);
            mma16816(acc[mf][1], ah[mf], bh[1], bh[3]);
            mma16816(acc[mf][1], ah[mf], bl[1], bl[3]);
            mma16816(acc[mf][1], al[mf], bh[1], bh[3]);
        }
    }

    // ---- epilogue: +b2, store y ----
    const float *b2h = b2 + hd * FOUT;
    #pragma unroll
    for (int nf = 0; nf < 2; nf++) {
        const int col = wn * 16 + nf * 8 + tig * 2;
        const float be = b2h[col], bo = b2h[col + 1];
        #pragma unroll
        for (int mf = 0; mf < 2; mf++) {
            const int r0 = n0 + wm * 32 + mf * 16 + gid;
            const int r1 = r0 + 8;
            if (r0 < N) {
                float2 t; t.x = acc[mf][nf][0] + be; t.y = acc[mf][nf][1] + bo;
                *reinterpret_cast<float2 *>(out + ((size_t)r0 * H + hd) * FOUT + col) = t;
            }
            if (r1 < N) {
                float2 t; t.x = acc[mf][nf][2] + be; t.y = acc[mf][nf][3] + bo;
                *reinterpret_cast<float2 *>(out + ((size_t)r1 * H + hd) * FOUT + col) = t;
            }
        }
    }
}

// ---------------------------------------------------------------------------
extern "C" void kernel_launch(void *const *d_in, const int *in_sizes, int n_in,
                              void *d_out, int out_size)
{
    (void)n_in; (void)out_size;
    const float *x    = (const float *)d_in[0];
    const float *w1   = (const float *)d_in[1];
    const float *b1   = (const float *)d_in[2];
    const float *bn_w = (const float *)d_in[3];
    const float *bn_b = (const float *)d_in[4];
    const float *w2   = (const float *)d_in[5];
    const float *b2   = (const float *)d_in[6];
    float *out = (float *)d_out;

    const int N = in_sizes[0] / (H * FIN);
    const int NT = (N + 127) / 128;

    const int SM1 = (2 * 128 * LDA + 2 * 64 * LDA) * 2 + 2 * 4 * 64 * 4;  // 106496 B
    const int SM3 = (2 * 128 * LDA + 2 * 64 * LDA) * 2 + 2 * HID * 4;     // 105472 B

    cudaFuncSetAttribute(k_gemm1, cudaFuncAttributeMaxDynamicSharedMemorySize, SM1);
    cudaFuncSetAttribute(k_gemm2, cudaFuncAttributeMaxDynamicSharedMemorySize, SM3);

    k_prep<<<H, 512>>>(w1, w2);
    k_gemm1<<<dim3(NT, H * 2), 512, SM1>>>(x, b1, N, NT);
    k_stats_a<<<dim3(H, NCH), HID>>>(NT);
    k_stats_b<<<H, HID>>>(bn_w, bn_b, N);
    k_gemm2<<<dim3(NT, H), 512, SM3>>>(b2, out, N);
}

// round 10
// speedup vs baseline: 1.0232x; 1.0118x over previous
// GroupMLP round 9 — revert to measured-best round-2 structure;
// gemm1: 128x128 tile, 512thr, 32x32 warps, 1 CTA/SM, + cp.async pre-split B fill
// gemm2: 128x64 tile, 512thr, 32x16 warps, 2 CTAs/SM (round-8 version)
#include <cuda_runtime.h>
#include <cuda_bf16.h>

#define H 8
#define FIN 128
#define HID 128
#define FOUT 64
#define LDA 136          // padded smem stride (elems): 272B rows -> ldmatrix conflict-free
#define NMAX 131072
#define NTMAX (NMAX / 128)
#define NCH 16

// Scratch (static device globals; no runtime allocation)
__device__ float g_h[(size_t)NMAX * H * HID];         // intermediate h [N,H,HID]
__device__ float g_psum[(size_t)H * NTMAX * HID];     // per-tile column sums
__device__ float g_psumsq[(size_t)H * NTMAX * HID];
__device__ float g_ps2[H * NCH * HID];
__device__ float g_pq2[H * NCH * HID];
__device__ float g_scale[H * HID];
__device__ float g_shift[H * HID];

// Pre-split weights, already in smem layout [n][k] with LDA stride
__device__ __nv_bfloat16 g_w1hi[H * 128 * LDA];
__device__ __nv_bfloat16 g_w1lo[H * 128 * LDA];
__device__ __nv_bfloat16 g_w2hi[H * 64 * LDA];
__device__ __nv_bfloat16 g_w2lo[H * 64 * LDA];

__device__ __forceinline__ void bsplit(float f, __nv_bfloat16 &hi, __nv_bfloat16 &lo) {
    hi = __float2bfloat16(f);
    lo = __float2bfloat16(f - __bfloat162float(hi));
}

__device__ __forceinline__ unsigned packbf2(__nv_bfloat16 a, __nv_bfloat16 b) {
    __nv_bfloat162 t; t.x = a; t.y = b;
    return *reinterpret_cast<unsigned *>(&t);
}

// 8-byte packed store of 4 bf16
__device__ __forceinline__ void st_bf4(__nv_bfloat16 *p, __nv_bfloat16 a, __nv_bfloat16 b,
                                       __nv_bfloat16 c, __nv_bfloat16 d) {
    uint2 t; t.x = packbf2(a, b); t.y = packbf2(c, d);
    *reinterpret_cast<uint2 *>(p) = t;
}

__device__ __forceinline__ void cpasync16(unsigned saddr, const void *gaddr) {
    asm volatile("cp.async.ca.shared.global [%0], [%1], 16;\n" :: "r"(saddr), "l"(gaddr));
}
__device__ __forceinline__ void cpasync_commit() { asm volatile("cp.async.commit_group;\n"); }
__device__ __forceinline__ void cpasync_wait0()  { asm volatile("cp.async.wait_group 0;\n"); }

__device__ __forceinline__ void ldsm4(unsigned &r0, unsigned &r1, unsigned &r2, unsigned &r3,
                                      unsigned addr) {
    asm volatile("ldmatrix.sync.aligned.m8n8.x4.shared.b16 {%0,%1,%2,%3}, [%4];\n"
                 : "=r"(r0), "=r"(r1), "=r"(r2), "=r"(r3) : "r"(addr));
}

__device__ __forceinline__ void mma16816(float c[4], const unsigned a[4],
                                         unsigned b0, unsigned b1) {
    asm volatile(
        "mma.sync.aligned.m16n8k16.row.col.f32.bf16.bf16.f32 "
        "{%0,%1,%2,%3}, {%4,%5,%6,%7}, {%8,%9}, {%0,%1,%2,%3};\n"
        : "+f"(c[0]), "+f"(c[1]), "+f"(c[2]), "+f"(c[3])
        : "r"(a[0]), "r"(a[1]), "r"(a[2]), "r"(a[3]), "r"(b0), "r"(b1));
}

// ---------------------------------------------------------------------------
// K0: pre-split weights into bf16 hi/lo, transposed to [n][k]*LDA layout.
// ---------------------------------------------------------------------------
__global__ void k_prep(const float *__restrict__ w1, const float *__restrict__ w2)
{
    const int hd = blockIdx.x;
    const int tid = threadIdx.x;
    const float *w1h = w1 + (size_t)hd * FIN * HID;
    __nv_bfloat16 *o1h = g_w1hi + (size_t)hd * 128 * LDA;
    __nv_bfloat16 *o1l = g_w1lo + (size_t)hd * 128 * LDA;
    for (int i = tid; i < 128 * 128; i += blockDim.x) {
        int n = i & 127, k = i >> 7;
        float f = w1h[(size_t)k * HID + n];
        __nv_bfloat16 hi, lo; bsplit(f, hi, lo);
        o1h[n * LDA + k] = hi; o1l[n * LDA + k] = lo;
    }
    const float *w2h = w2 + (size_t)hd * HID * FOUT;
    __nv_bfloat16 *o2h = g_w2hi + (size_t)hd * 64 * LDA;
    __nv_bfloat16 *o2l = g_w2lo + (size_t)hd * 64 * LDA;
    for (int i = tid; i < 64 * 128; i += blockDim.x) {
        int n = i & 63, k = i >> 6;
        float f = w2h[(size_t)k * FOUT + n];
        __nv_bfloat16 hi, lo; bsplit(f, hi, lo);
        o2h[n * LDA + k] = hi; o2l[n * LDA + k] = lo;
    }
}

// ---------------------------------------------------------------------------
// K1: h = x @ w1 + b1 (per head), 3-pass bf16-split MMA, fp32 accum.
// 512 threads, block tile 128x128, warp grid 4m x 4n (warp tile 32x32).
// B cp.async'd from pre-split weights; batched A-fill. Writes h + tile stats.
// ---------------------------------------------------------------------------
__global__ void __launch_bounds__(512, 1)
k_gemm1(const float *__restrict__ x, const float *__restrict__ b1, int N, int NT)
{
    extern __shared__ unsigned char smraw[];
    __nv_bfloat16 *Ahi = (__nv_bfloat16 *)smraw;
    __nv_bfloat16 *Alo = Ahi + 128 * LDA;
    __nv_bfloat16 *Bhi = Alo + 128 * LDA;
    __nv_bfloat16 *Blo = Bhi + 128 * LDA;
    float *psS = (float *)(Blo + 128 * LDA);   // [4][HID]
    float *pqS = psS + 4 * HID;                // [4][HID]

    const int tid = threadIdx.x;
    const int hd = blockIdx.y;
    const int n0 = blockIdx.x * 128;

    // ---- kick off B fill via cp.async (pre-split, already in layout) ----
    {
        unsigned sBhi = (unsigned)__cvta_generic_to_shared(Bhi);
        unsigned sBlo = (unsigned)__cvta_generic_to_shared(Blo);
        const __nv_bfloat16 *srcHi = g_w1hi + (size_t)hd * 128 * LDA;
        const __nv_bfloat16 *srcLo = g_w1lo + (size_t)hd * 128 * LDA;
        const int NCHK = 128 * LDA / 8;        // 2176 16B chunks per plane
        for (int i = tid; i < NCHK; i += 512) {
            cpasync16(sBhi + i * 16, srcHi + i * 8);
            cpasync16(sBlo + i * 16, srcLo + i * 8);
        }
        cpasync_commit();
    }

    // ---- fill A (x tile): batched LDG (MLP=8), then convert+store ----
    {
        float4 v[8];
        #pragma unroll
        for (int ii = 0; ii < 8; ii++) {
            int i = tid + ii * 512;
            int r = i >> 5, c4 = (i & 31) << 2;
            int row = n0 + r;
            v[ii] = make_float4(0.f, 0.f, 0.f, 0.f);
            if (row < N)
                v[ii] = *reinterpret_cast<const float4 *>(x + ((size_t)row * H + hd) * FIN + c4);
        }
        #pragma unroll
        for (int ii = 0; ii < 8; ii++) {
            int i = tid + ii * 512;
            int r = i >> 5, c4 = (i & 31) << 2;
            __nv_bfloat16 h0, h1, h2, h3, l0, l1, l2, l3;
            bsplit(v[ii].x, h0, l0); bsplit(v[ii].y, h1, l1);
            bsplit(v[ii].z, h2, l2); bsplit(v[ii].w, h3, l3);
            st_bf4(Ahi + r * LDA + c4, h0, h1, h2, h3);
            st_bf4(Alo + r * LDA + c4, l0, l1, l2, l3);
        }
    }
    cpasync_wait0();
    __syncthreads();

    const int lane = tid & 31;
    const int w = tid >> 5;
    const int gid = lane >> 2, tig = lane & 3;
    const int wm = w & 3, wn = w >> 2;     // warp tile: rows wm*32.., cols wn*32..

    const int lr = lane & 15;
    const int kh = ((lane >> 4) & 1) << 3;
    unsigned sAhi = (unsigned)__cvta_generic_to_shared(Ahi);
    unsigned sAlo = (unsigned)__cvta_generic_to_shared(Alo);
    unsigned sBhi = (unsigned)__cvta_generic_to_shared(Bhi);
    unsigned sBlo = (unsigned)__cvta_generic_to_shared(Blo);
    unsigned aHiAd[2], aLoAd[2], bHiAd[2], bLoAd[2];
    #pragma unroll
    for (int mf = 0; mf < 2; mf++) {
        unsigned off = ((wm * 32 + mf * 16 + lr) * LDA + kh) * 2;
        aHiAd[mf] = sAhi + off; aLoAd[mf] = sAlo + off;
    }
    #pragma unroll
    for (int g = 0; g < 2; g++) {
        unsigned off = ((wn * 32 + g * 16 + lr) * LDA + kh) * 2;
        bHiAd[g] = sBhi + off; bLoAd[g] = sBlo + off;
    }

    float acc[2][4][4];
    #pragma unroll
    for (int mf = 0; mf < 2; mf++)
        #pragma unroll
        for (int nf = 0; nf < 4; nf++)
            #pragma unroll
            for (int q = 0; q < 4; q++) acc[mf][nf][q] = 0.f;

    #pragma unroll
    for (int kc = 0; kc < 8; kc++) {
        const unsigned kadv = kc * 32;          // 16 elems * 2B
        unsigned ah[2][4], al[2][4], bh[2][4], bl[2][4];
        #pragma unroll
        for (int mf = 0; mf < 2; mf++) {
            ldsm4(ah[mf][0], ah[mf][1], ah[mf][2], ah[mf][3], aHiAd[mf] + kadv);
            ldsm4(al[mf][0], al[mf][1], al[mf][2], al[mf][3], aLoAd[mf] + kadv);
        }
        #pragma unroll
        for (int g = 0; g < 2; g++) {
            ldsm4(bh[g][0], bh[g][1], bh[g][2], bh[g][3], bHiAd[g] + kadv);
            ldsm4(bl[g][0], bl[g][1], bl[g][2], bl[g][3], bLoAd[g] + kadv);
        }
        #pragma unroll
        for (int mf = 0; mf < 2; mf++)
            #pragma unroll
            for (int g = 0; g < 2; g++) {
                // sub-group 0: cols g*16 + 0..7 -> b-frag {r0, r2}
                mma16816(acc[mf][g * 2 + 0], ah[mf], bh[g][0], bh[g][2]);
                mma16816(acc[mf][g * 2 + 0], ah[mf], bl[g][0], bl[g][2]);
                mma16816(acc[mf][g * 2 + 0], al[mf], bh[g][0], bh[g][2]);
                // sub-group 1: cols g*16 + 8..15 -> b-frag {r1, r3}
                mma16816(acc[mf][g * 2 + 1], ah[mf], bh[g][1], bh[g][3]);
                mma16816(acc[mf][g * 2 + 1], ah[mf], bl[g][1], bl[g][3]);
                mma16816(acc[mf][g * 2 + 1], al[mf], bh[g][1], bh[g][3]);
            }
    }

    // ---- epilogue: +b1, store h, per-column stats ----
    const float *b1h = b1 + hd * HID;
    #pragma unroll
    for (int nf = 0; nf < 4; nf++) {
        const int col = wn * 32 + nf * 8 + tig * 2;
        const float be = b1h[col], bo = b1h[col + 1];
        float se = 0.f, qe = 0.f, so = 0.f, qo = 0.f;
        #pragma unroll
        for (int mf = 0; mf < 2; mf++) {
            const int r0 = n0 + wm * 32 + mf * 16 + gid;
            const int r1 = r0 + 8;
            float v0 = acc[mf][nf][0] + be;
            float v1 = acc[mf][nf][1] + bo;
            float v2 = acc[mf][nf][2] + be;
            float v3 = acc[mf][nf][3] + bo;
            if (r0 < N) {
                float2 t; t.x = v0; t.y = v1;
                *reinterpret_cast<float2 *>(g_h + ((size_t)r0 * H + hd) * HID + col) = t;
                se += v0; qe += v0 * v0; so += v1; qo += v1 * v1;
            }
            if (r1 < N) {
                float2 t; t.x = v2; t.y = v3;
                *reinterpret_cast<float2 *>(g_h + ((size_t)r1 * H + hd) * HID + col) = t;
                se += v2; qe += v2 * v2; so += v3; qo += v3 * v3;
            }
        }
        #pragma unroll
        for (int off = 16; off >= 4; off >>= 1) {
            se += __shfl_xor_sync(0xffffffffu, se, off);
            so += __shfl_xor_sync(0xffffffffu, so, off);
            qe += __shfl_xor_sync(0xffffffffu, qe, off);
            qo += __shfl_xor_sync(0xffffffffu, qo, off);
        }
        if (gid == 0) {
            psS[wm * HID + col] = se; psS[wm * HID + col + 1] = so;
            pqS[wm * HID + col] = qe; pqS[wm * HID + col + 1] = qo;
        }
    }
    __syncthreads();
    if (tid < HID) {
        float s = psS[tid] + psS[HID + tid] + psS[2 * HID + tid] + psS[3 * HID + tid];
        float q = pqS[tid] + pqS[HID + tid] + pqS[2 * HID + tid] + pqS[3 * HID + tid];
        size_t o = ((size_t)hd * NT + blockIdx.x) * HID + tid;
        g_psum[o] = s; g_psumsq[o] = q;
    }
}

// ---------------------------------------------------------------------------
// K2a/K2b: deterministic fixed-order reduction of tile stats -> BN scale/shift
// ---------------------------------------------------------------------------
__global__ void k_stats_a(int NT)
{
    const int hd = blockIdx.x, ch = blockIdx.y, c = threadIdx.x;
    const int per = (NT + NCH - 1) / NCH;
    int t0 = ch * per;
    int t1 = min(NT, t0 + per);
    const float *ps = g_psum + (size_t)hd * NT * HID + c;
    const float *pq = g_psumsq + (size_t)hd * NT * HID + c;
    float s0 = 0, s1 = 0, s2 = 0, s3 = 0, q0 = 0, q1 = 0, q2 = 0, q3 = 0;
    int t = t0;
    for (; t + 4 <= t1; t += 4) {
        s0 += ps[(size_t)(t + 0) * HID]; q0 += pq[(size_t)(t + 0) * HID];
        s1 += ps[(size_t)(t + 1) * HID]; q1 += pq[(size_t)(t + 1) * HID];
        s2 += ps[(size_t)(t + 2) * HID]; q2 += pq[(size_t)(t + 2) * HID];
        s3 += ps[(size_t)(t + 3) * HID]; q3 += pq[(size_t)(t + 3) * HID];
    }
    for (; t < t1; t++) { s0 += ps[(size_t)t * HID]; q0 += pq[(size_t)t * HID]; }
    g_ps2[(hd * NCH + ch) * HID + c] = (s0 + s1) + (s2 + s3);
    g_pq2[(hd * NCH + ch) * HID + c] = (q0 + q1) + (q2 + q3);
}

__global__ void k_stats_b(const float *__restrict__ bn_w, const float *__restrict__ bn_b, int N)
{
    const int hd = blockIdx.x, c = threadIdx.x;
    float s = 0.f, q = 0.f;
    #pragma unroll
    for (int ch = 0; ch < NCH; ch++) {
        s += g_ps2[(hd * NCH + ch) * HID + c];
        q += g_pq2[(hd * NCH + ch) * HID + c];
    }
    float invN = 1.0f / (float)N;
    float mean = s * invN;
    float var = fmaxf(q * invN - mean * mean, 0.f);
    float inv = rsqrtf(var + 1e-5f);
    float sc = bn_w[hd * HID + c] * inv;
    g_scale[hd * HID + c] = sc;
    g_shift[hd * HID + c] = bn_b[hd * HID + c] - mean * sc;
}

// ---------------------------------------------------------------------------
// K3: y = relu(h*scale + shift) @ w2 + b2, 3-pass bf16-split MMA.
// 512 threads, block tile 128x64, warp grid 4x4 (warp tile 32x16), 2 CTAs/SM.
// ---------------------------------------------------------------------------
__global__ void __launch_bounds__(512, 2)
k_gemm2(const float *__restrict__ b2, float *__restrict__ out, int N)
{
    extern __shared__ unsigned char smraw[];
    __nv_bfloat16 *Ahi = (__nv_bfloat16 *)smraw;
    __nv_bfloat16 *Alo = Ahi + 128 * LDA;
    __nv_bfloat16 *Bhi = Alo + 128 * LDA;
    __nv_bfloat16 *Blo = Bhi + 64 * LDA;
    float *scS = (float *)(Blo + 64 * LDA);
    float *shS = scS + HID;

    const int tid = threadIdx.x;
    const int hd = blockIdx.y;
    const int n0 = blockIdx.x * 128;

    // ---- kick off B fill via cp.async ----
    {
        unsigned sBhi = (unsigned)__cvta_generic_to_shared(Bhi);
        unsigned sBlo = (unsigned)__cvta_generic_to_shared(Blo);
        const __nv_bfloat16 *srcHi = g_w2hi + (size_t)hd * 64 * LDA;
        const __nv_bfloat16 *srcLo = g_w2lo + (size_t)hd * 64 * LDA;
        const int NCHK = 64 * LDA / 8;
        for (int i = tid; i < NCHK; i += 512) {
            cpasync16(sBhi + i * 16, srcHi + i * 8);
            cpasync16(sBlo + i * 16, srcLo + i * 8);
        }
        cpasync_commit();
    }

    if (tid < HID) {
        scS[tid] = g_scale[hd * HID + tid];
        shS[tid] = g_shift[hd * HID + tid];
    }
    __syncthreads();

    // ---- fill A = relu(h*s + t): batched LDG, then convert+store ----
    {
        float4 v[8];
        #pragma unroll
        for (int ii = 0; ii < 8; ii++) {
            int i = tid + ii * 512;
            int r = i >> 5, c4 = (i & 31) << 2;
            int row = n0 + r;
            v[ii] = make_float4(0.f, 0.f, 0.f, 0.f);
            if (row < N)
                v[ii] = *reinterpret_cast<const float4 *>(g_h + ((size_t)row * H + hd) * HID + c4);
        }
        #pragma unroll
        for (int ii = 0; ii < 8; ii++) {
            int i = tid + ii * 512;
            int r = i >> 5, c4 = (i & 31) << 2;
            int row = n0 + r;
            float4 sc = *reinterpret_cast<const float4 *>(scS + c4);
            float4 sh = *reinterpret_cast<const float4 *>(shS + c4);
            float a0 = fmaxf(v[ii].x * sc.x + sh.x, 0.f);
            float a1 = fmaxf(v[ii].y * sc.y + sh.y, 0.f);
            float a2 = fmaxf(v[ii].z * sc.z + sh.z, 0.f);
            float a3 = fmaxf(v[ii].w * sc.w + sh.w, 0.f);
            if (row >= N) { a0 = a1 = a2 = a3 = 0.f; }
            __nv_bfloat16 h0, h1, h2, h3, l0, l1, l2, l3;
            bsplit(a0, h0, l0); bsplit(a1, h1, l1);
            bsplit(a2, h2, l2); bsplit(a3, h3, l3);
            st_bf4(Ahi + r * LDA + c4, h0, h1, h2, h3);
            st_bf4(Alo + r * LDA + c4, l0, l1, l2, l3);
        }
    }
    cpasync_wait0();
    __syncthreads();

    const int lane = tid & 31;
    const int w = tid >> 5;
    const int gid = lane >> 2, tig = lane & 3;
    const int wm = w & 3, wn = w >> 2;     // warp tile: rows wm*32.., cols wn*16..

    const int lr = lane & 15;
    const int kh = ((lane >> 4) & 1) << 3;
    unsigned sAhi = (unsigned)__cvta_generic_to_shared(Ahi);
    unsigned sAlo = (unsigned)__cvta_generic_to_shared(Alo);
    unsigned sBhi = (unsigned)__cvta_generic_to_shared(Bhi);
    unsigned sBlo = (unsigned)__cvta_generic_to_shared(Blo);
    unsigned aHiAd[2], aLoAd[2], bHiAd, bLoAd;
    #pragma unroll
    for (int mf = 0; mf < 2; mf++) {
        unsigned off = ((wm * 32 + mf * 16 + lr) * LDA + kh) * 2;
        aHiAd[mf] = sAhi + off; aLoAd[mf] = sAlo + off;
    }
    {
        unsigned off = ((wn * 16 + lr) * LDA + kh) * 2;
        bHiAd = sBhi + off; bLoAd = sBlo + off;
    }

    float acc[2][2][4];
    #pragma unroll
    for (int mf = 0; mf < 2; mf++)
        #pragma unroll
        for (int nf = 0; nf < 2; nf++)
            #pragma unroll
            for (int q = 0; q < 4; q++) acc[mf][nf][q] = 0.f;

    #pragma unroll
    for (int kc = 0; kc < 8; kc++) {
        const unsigned kadv = kc * 32;
        unsigned ah[2][4], al[2][4], bh[4], bl[4];
        #pragma unroll
        for (int mf = 0; mf < 2; mf++) {
            ldsm4(ah[mf][0], ah[mf][1], ah[mf][2], ah[mf][3], aHiAd[mf] + kadv);
            ldsm4(al[mf][0], al[mf][1], al[mf][2], al[mf][3], aLoAd[mf] + kadv);
        }
        ldsm4(bh[0], bh[1], bh[2], bh[3], bHiAd + kadv);
        ldsm4(bl[0], bl[1], bl[2], bl[3], bLoAd + kadv);
        #pragma unroll
        for (int mf = 0; mf < 2; mf++) {
            mma16816(acc[mf][0], ah[mf], bh[0], bh[2]);
            mma16816(acc[mf][0], ah[mf], bl[0], bl[2]);
            mma16816(acc[mf][0], al[mf], bh[0], bh[2]);
            mma16816(acc[mf][1], ah[mf], bh[1], bh[3]);
            mma16816(acc[mf][1], ah[mf], bl[1], bl[3]);
            mma16816(acc[mf][1], al[mf], bh[1], bh[3]);
        }
    }

    // ---- epilogue: +b2, store y ----
    const float *b2h = b2 + hd * FOUT;
    #pragma unroll
    for (int nf = 0; nf < 2; nf++) {
        const int col = wn * 16 + nf * 8 + tig * 2;
        const float be = b2h[col], bo = b2h[col + 1];
        #pragma unroll
        for (int mf = 0; mf < 2; mf++) {
            const int r0 = n0 + wm * 32 + mf * 16 + gid;
            const int r1 = r0 + 8;
            if (r0 < N) {
                float2 t; t.x = acc[mf][nf][0] + be; t.y = acc[mf][nf][1] + bo;
                *reinterpret_cast<float2 *>(out + ((size_t)r0 * H + hd) * FOUT + col) = t;
            }
            if (r1 < N) {
                float2 t; t.x = acc[mf][nf][2] + be; t.y = acc[mf][nf][3] + bo;
                *reinterpret_cast<float2 *>(out + ((size_t)r1 * H + hd) * FOUT + col) = t;
            }
        }
    }
}

// ---------------------------------------------------------------------------
extern "C" void kernel_launch(void *const *d_in, const int *in_sizes, int n_in,
                              void *d_out, int out_size)
{
    (void)n_in; (void)out_size;
    const float *x    = (const float *)d_in[0];
    const float *w1   = (const float *)d_in[1];
    const float *b1   = (const float *)d_in[2];
    const float *bn_w = (const float *)d_in[3];
    const float *bn_b = (const float *)d_in[4];
    const float *w2   = (const float *)d_in[5];
    const float *b2   = (const float *)d_in[6];
    float *out = (float *)d_out;

    const int N = in_sizes[0] / (H * FIN);
    const int NT = (N + 127) / 128;

    const int SM1 = 4 * 128 * LDA * 2 + 2 * 4 * HID * 4;               // 143360 B
    const int SM3 = (2 * 128 * LDA + 2 * 64 * LDA) * 2 + 2 * HID * 4;  // 105472 B

    cudaFuncSetAttribute(k_gemm1, cudaFuncAttributeMaxDynamicSharedMemorySize, SM1);
    cudaFuncSetAttribute(k_gemm2, cudaFuncAttributeMaxDynamicSharedMemorySize, SM3);

    k_prep<<<H, 512>>>(w1, w2);
    k_gemm1<<<dim3(NT, H), 512, SM1>>>(x, b1, N, NT);
    k_stats_a<<<dim3(H, NCH), HID>>>(NT);
    k_stats_b<<<H, HID>>>(bn_w, bn_b, N);
    k_gemm2<<<dim3(NT, H), 512, SM3>>>(b2, out, N);
}

// round 13
// speedup vs baseline: 1.3597x; 1.3289x over previous
// GroupMLP round 11 — fp16 2-pass scheme: A single-plane fp16, B = wh+wl fp16
// split, passes Ah*Bh + Ah*Bl. Halves A smem -> gemm1 128x128 tile now fits
// 2 CTAs/SM; -33% MMA instructions in both GEMMs.
#include <cuda_runtime.h>
#include <cuda_fp16.h>

#define H 8
#define FIN 128
#define HID 128
#define FOUT 64
#define LDA 136          // padded smem stride (elems): 272B rows -> ldmatrix conflict-free
#define NMAX 131072
#define NTMAX (NMAX / 128)
#define NCH 16

// Scratch (static device globals; no runtime allocation)
__device__ float g_h[(size_t)NMAX * H * HID];         // intermediate h [N,H,HID]
__device__ float g_psum[(size_t)H * NTMAX * HID];     // per-tile column sums
__device__ float g_psumsq[(size_t)H * NTMAX * HID];
__device__ float g_ps2[H * NCH * HID];
__device__ float g_pq2[H * NCH * HID];
__device__ float g_scale[H * HID];
__device__ float g_shift[H * HID];

// Pre-split fp16 weights (hi + residual lo), already in [n][k]*LDA smem layout
__device__ __half g_w1hi[H * 128 * LDA];
__device__ __half g_w1lo[H * 128 * LDA];
__device__ __half g_w2hi[H * 64 * LDA];
__device__ __half g_w2lo[H * 64 * LDA];

__device__ __forceinline__ void hsplit(float f, __half &hi, __half &lo) {
    hi = __float2half_rn(f);
    lo = __float2half_rn(f - __half2float(hi));
}

// 8-byte packed store of 4 fp16
__device__ __forceinline__ void st_h4(__half *p, __half a, __half b, __half c, __half d) {
    __half2 t0 = __halves2half2(a, b);
    __half2 t1 = __halves2half2(c, d);
    uint2 t;
    t.x = *reinterpret_cast<unsigned *>(&t0);
    t.y = *reinterpret_cast<unsigned *>(&t1);
    *reinterpret_cast<uint2 *>(p) = t;
}

__device__ __forceinline__ void cpasync16(unsigned saddr, const void *gaddr) {
    asm volatile("cp.async.ca.shared.global [%0], [%1], 16;\n" :: "r"(saddr), "l"(gaddr));
}
__device__ __forceinline__ void cpasync_commit() { asm volatile("cp.async.commit_group;\n"); }
__device__ __forceinline__ void cpasync_wait0()  { asm volatile("cp.async.wait_group 0;\n"); }

__device__ __forceinline__ void ldsm4(unsigned &r0, unsigned &r1, unsigned &r2, unsigned &r3,
                                      unsigned addr) {
    asm volatile("ldmatrix.sync.aligned.m8n8.x4.shared.b16 {%0,%1,%2,%3}, [%4];\n"
                 : "=r"(r0), "=r"(r1), "=r"(r2), "=r"(r3) : "r"(addr));
}

__device__ __forceinline__ void mma16816h(float c[4], const unsigned a[4],
                                          unsigned b0, unsigned b1) {
    asm volatile(
        "mma.sync.aligned.m16n8k16.row.col.f32.f16.f16.f32 "
        "{%0,%1,%2,%3}, {%4,%5,%6,%7}, {%8,%9}, {%0,%1,%2,%3};\n"
        : "+f"(c[0]), "+f"(c[1]), "+f"(c[2]), "+f"(c[3])
        : "r"(a[0]), "r"(a[1]), "r"(a[2]), "r"(a[3]), "r"(b0), "r"(b1));
}

// ---------------------------------------------------------------------------
// K0: pre-split weights into fp16 hi/lo, transposed to [n][k]*LDA layout.
// ---------------------------------------------------------------------------
__global__ void k_prep(const float *__restrict__ w1, const float *__restrict__ w2)
{
    const int hd = blockIdx.x;
    const int tid = threadIdx.x;
    const float *w1h = w1 + (size_t)hd * FIN * HID;
    __half *o1h = g_w1hi + (size_t)hd * 128 * LDA;
    __half *o1l = g_w1lo + (size_t)hd * 128 * LDA;
    for (int i = tid; i < 128 * 128; i += blockDim.x) {
        int n = i & 127, k = i >> 7;
        float f = w1h[(size_t)k * HID + n];
        __half hi, lo; hsplit(f, hi, lo);
        o1h[n * LDA + k] = hi; o1l[n * LDA + k] = lo;
    }
    const float *w2h = w2 + (size_t)hd * HID * FOUT;
    __half *o2h = g_w2hi + (size_t)hd * 64 * LDA;
    __half *o2l = g_w2lo + (size_t)hd * 64 * LDA;
    for (int i = tid; i < 64 * 128; i += blockDim.x) {
        int n = i & 63, k = i >> 6;
        float f = w2h[(size_t)k * FOUT + n];
        __half hi, lo; hsplit(f, hi, lo);
        o2h[n * LDA + k] = hi; o2l[n * LDA + k] = lo;
    }
}

// ---------------------------------------------------------------------------
// K1: h = x @ w1 + b1 (per head), 2-pass fp16 MMA (Ah*Bh + Ah*Bl), fp32 accum.
// 512 threads, block tile 128x128, warp grid 4m x 4n (warp tile 32x32).
// smem ~108.5KB -> 2 CTAs/SM. Writes h + per-tile stats.
// ---------------------------------------------------------------------------
__global__ void __launch_bounds__(512, 2)
k_gemm1(const float *__restrict__ x, const float *__restrict__ b1, int N, int NT)
{
    extern __shared__ unsigned char smraw[];
    __half *Ah  = (__half *)smraw;             // 128*LDA
    __half *Bhi = Ah + 128 * LDA;
    __half *Blo = Bhi + 128 * LDA;
    float *psS = (float *)(Blo + 128 * LDA);   // [4][HID]
    float *pqS = psS + 4 * HID;                // [4][HID]

    const int tid = threadIdx.x;
    const int hd = blockIdx.y;
    const int n0 = blockIdx.x * 128;

    // ---- kick off B fill via cp.async (pre-split, already in layout) ----
    {
        unsigned sBhi = (unsigned)__cvta_generic_to_shared(Bhi);
        unsigned sBlo = (unsigned)__cvta_generic_to_shared(Blo);
        const __half *srcHi = g_w1hi + (size_t)hd * 128 * LDA;
        const __half *srcLo = g_w1lo + (size_t)hd * 128 * LDA;
        const int NCHK = 128 * LDA / 8;        // 16B chunks per plane
        for (int i = tid; i < NCHK; i += 512) {
            cpasync16(sBhi + i * 16, srcHi + i * 8);
            cpasync16(sBlo + i * 16, srcLo + i * 8);
        }
        cpasync_commit();
    }

    // ---- fill A (x tile), single fp16 plane ----
    #pragma unroll
    for (int i = tid; i < 128 * 32; i += 512) {
        int r = i >> 5, c4 = (i & 31) << 2;
        float4 v = make_float4(0.f, 0.f, 0.f, 0.f);
        int row = n0 + r;
        if (row < N)
            v = *reinterpret_cast<const float4 *>(x + ((size_t)row * H + hd) * FIN + c4);
        st_h4(Ah + r * LDA + c4, __float2half_rn(v.x), __float2half_rn(v.y),
              __float2half_rn(v.z), __float2half_rn(v.w));
    }
    cpasync_wait0();
    __syncthreads();

    const int lane = tid & 31;
    const int w = tid >> 5;
    const int gid = lane >> 2, tig = lane & 3;
    const int wm = w & 3, wn = w >> 2;     // warp tile: rows wm*32.., cols wn*32..

    const int lr = lane & 15;
    const int kh = ((lane >> 4) & 1) << 3;
    unsigned sAh  = (unsigned)__cvta_generic_to_shared(Ah);
    unsigned sBhi = (unsigned)__cvta_generic_to_shared(Bhi);
    unsigned sBlo = (unsigned)__cvta_generic_to_shared(Blo);
    unsigned aAd[2], bHiAd[2], bLoAd[2];
    #pragma unroll
    for (int mf = 0; mf < 2; mf++)
        aAd[mf] = sAh + ((wm * 32 + mf * 16 + lr) * LDA + kh) * 2;
    #pragma unroll
    for (int g = 0; g < 2; g++) {
        unsigned off = ((wn * 32 + g * 16 + lr) * LDA + kh) * 2;
        bHiAd[g] = sBhi + off; bLoAd[g] = sBlo + off;
    }

    float acc[2][4][4];
    #pragma unroll
    for (int mf = 0; mf < 2; mf++)
        #pragma unroll
        for (int nf = 0; nf < 4; nf++)
            #pragma unroll
            for (int q = 0; q < 4; q++) acc[mf][nf][q] = 0.f;

    #pragma unroll
    for (int kc = 0; kc < 8; kc++) {
        const unsigned kadv = kc * 32;          // 16 elems * 2B
        unsigned ah[2][4];
        #pragma unroll
        for (int mf = 0; mf < 2; mf++)
            ldsm4(ah[mf][0], ah[mf][1], ah[mf][2], ah[mf][3], aAd[mf] + kadv);
        #pragma unroll
        for (int g = 0; g < 2; g++) {
            unsigned bh[4], bl[4];
            ldsm4(bh[0], bh[1], bh[2], bh[3], bHiAd[g] + kadv);
            ldsm4(bl[0], bl[1], bl[2], bl[3], bLoAd[g] + kadv);
            #pragma unroll
            for (int mf = 0; mf < 2; mf++) {
                // cols g*16 + 0..7 -> b-frag {r0, r2}; 8..15 -> {r1, r3}
                mma16816h(acc[mf][g * 2 + 0], ah[mf], bh[0], bh[2]);
                mma16816h(acc[mf][g * 2 + 0], ah[mf], bl[0], bl[2]);
                mma16816h(acc[mf][g * 2 + 1], ah[mf], bh[1], bh[3]);
                mma16816h(acc[mf][g * 2 + 1], ah[mf], bl[1], bl[3]);
            }
        }
    }

    // ---- epilogue: +b1, store h, per-column stats ----
    const float *b1h = b1 + hd * HID;
    #pragma unroll
    for (int nf = 0; nf < 4; nf++) {
        const int col = wn * 32 + nf * 8 + tig * 2;
        const float be = b1h[col], bo = b1h[col + 1];
        float se = 0.f, qe = 0.f, so = 0.f, qo = 0.f;
        #pragma unroll
        for (int mf = 0; mf < 2; mf++) {
            const int r0 = n0 + wm * 32 + mf * 16 + gid;
            const int r1 = r0 + 8;
            float v0 = acc[mf][nf][0] + be;
            float v1 = acc[mf][nf][1] + bo;
            float v2 = acc[mf][nf][2] + be;
            float v3 = acc[mf][nf][3] + bo;
            if (r0 < N) {
                float2 t; t.x = v0; t.y = v1;
                *reinterpret_cast<float2 *>(g_h + ((size_t)r0 * H + hd) * HID + col) = t;
                se += v0; qe += v0 * v0; so += v1; qo += v1 * v1;
            }
            if (r1 < N) {
                float2 t; t.x = v2; t.y = v3;
                *reinterpret_cast<float2 *>(g_h + ((size_t)r1 * H + hd) * HID + col) = t;
                se += v2; qe += v2 * v2; so += v3; qo += v3 * v3;
            }
        }
        #pragma unroll
        for (int off = 16; off >= 4; off >>= 1) {
            se += __shfl_xor_sync(0xffffffffu, se, off);
            so += __shfl_xor_sync(0xffffffffu, so, off);
            qe += __shfl_xor_sync(0xffffffffu, qe, off);
            qo += __shfl_xor_sync(0xffffffffu, qo, off);
        }
        if (gid == 0) {
            psS[wm * HID + col] = se; psS[wm * HID + col + 1] = so;
            pqS[wm * HID + col] = qe; pqS[wm * HID + col + 1] = qo;
        }
    }
    __syncthreads();
    if (tid < HID) {
        float s = psS[tid] + psS[HID + tid] + psS[2 * HID + tid] + psS[3 * HID + tid];
        float q = pqS[tid] + pqS[HID + tid] + pqS[2 * HID + tid] + pqS[3 * HID + tid];
        size_t o = ((size_t)hd * NT + blockIdx.x) * HID + tid;
        g_psum[o] = s; g_psumsq[o] = q;
    }
}

// ---------------------------------------------------------------------------
// K2a/K2b: deterministic fixed-order reduction of tile stats -> BN scale/shift
// ---------------------------------------------------------------------------
__global__ void k_stats_a(int NT)
{
    const int hd = blockIdx.x, ch = blockIdx.y, c = threadIdx.x;
    const int per = (NT + NCH - 1) / NCH;
    int t0 = ch * per;
    int t1 = min(NT, t0 + per);
    const float *ps = g_psum + (size_t)hd * NT * HID + c;
    const float *pq = g_psumsq + (size_t)hd * NT * HID + c;
    float s0 = 0, s1 = 0, s2 = 0, s3 = 0, q0 = 0, q1 = 0, q2 = 0, q3 = 0;
    int t = t0;
    for (; t + 4 <= t1; t += 4) {
        s0 += ps[(size_t)(t + 0) * HID]; q0 += pq[(size_t)(t + 0) * HID];
        s1 += ps[(size_t)(t + 1) * HID]; q1 += pq[(size_t)(t + 1) * HID];
        s2 += ps[(size_t)(t + 2) * HID]; q2 += pq[(size_t)(t + 2) * HID];
        s3 += ps[(size_t)(t + 3) * HID]; q3 += pq[(size_t)(t + 3) * HID];
    }
    for (; t < t1; t++) { s0 += ps[(size_t)t * HID]; q0 += pq[(size_t)t * HID]; }
    g_ps2[(hd * NCH + ch) * HID + c] = (s0 + s1) + (s2 + s3);
    g_pq2[(hd * NCH + ch) * HID + c] = (q0 + q1) + (q2 + q3);
}

__global__ void k_stats_b(const float *__restrict__ bn_w, const float *__restrict__ bn_b, int N)
{
    const int hd = blockIdx.x, c = threadIdx.x;
    float s = 0.f, q = 0.f;
    #pragma unroll
    for (int ch = 0; ch < NCH; ch++) {
        s += g_ps2[(hd * NCH + ch) * HID + c];
        q += g_pq2[(hd * NCH + ch) * HID + c];
    }
    float invN = 1.0f / (float)N;
    float mean = s * invN;
    float var = fmaxf(q * invN - mean * mean, 0.f);
    float inv = rsqrtf(var + 1e-5f);
    float sc = bn_w[hd * HID + c] * inv;
    g_scale[hd * HID + c] = sc;
    g_shift[hd * HID + c] = bn_b[hd * HID + c] - mean * sc;
}

// ---------------------------------------------------------------------------
// K3: y = relu(h*scale + shift) @ w2 + b2, 2-pass fp16 MMA.
// 512 threads, block tile 128x64, warp grid 4x4 (warp tile 32x16), 2 CTAs/SM.
// ---------------------------------------------------------------------------
__global__ void __launch_bounds__(512, 2)
k_gemm2(const float *__restrict__ b2, float *__restrict__ out, int N)
{
    extern __shared__ unsigned char smraw[];
    __half *Ah  = (__half *)smraw;             // 128*LDA
    __half *Bhi = Ah + 128 * LDA;
    __half *Blo = Bhi + 64 * LDA;
    float *scS = (float *)(Blo + 64 * LDA);
    float *shS = scS + HID;

    const int tid = threadIdx.x;
    const int hd = blockIdx.y;
    const int n0 = blockIdx.x * 128;

    // ---- kick off B fill via cp.async ----
    {
        unsigned sBhi = (unsigned)__cvta_generic_to_shared(Bhi);
        unsigned sBlo = (unsigned)__cvta_generic_to_shared(Blo);
        const __half *srcHi = g_w2hi + (size_t)hd * 64 * LDA;
        const __half *srcLo = g_w2lo + (size_t)hd * 64 * LDA;
        const int NCHK = 64 * LDA / 8;
        for (int i = tid; i < NCHK; i += 512) {
            cpasync16(sBhi + i * 16, srcHi + i * 8);
            cpasync16(sBlo + i * 16, srcLo + i * 8);
        }
        cpasync_commit();
    }

    if (tid < HID) {
        scS[tid] = g_scale[hd * HID + tid];
        shS[tid] = g_shift[hd * HID + tid];
    }
    __syncthreads();

    // ---- fill A = relu(h*s + t), single fp16 plane ----
    #pragma unroll
    for (int i = tid; i < 128 * 32; i += 512) {
        int r = i >> 5, c4 = (i & 31) << 2;
        int row = n0 + r;
        float4 v = make_float4(0.f, 0.f, 0.f, 0.f);
        if (row < N)
            v = *reinterpret_cast<const float4 *>(g_h + ((size_t)row * H + hd) * HID + c4);
        float4 sc = *reinterpret_cast<const float4 *>(scS + c4);
        float4 sh = *reinterpret_cast<const float4 *>(shS + c4);
        float a0 = fmaxf(v.x * sc.x + sh.x, 0.f);
        float a1 = fmaxf(v.y * sc.y + sh.y, 0.f);
        float a2 = fmaxf(v.z * sc.z + sh.z, 0.f);
        float a3 = fmaxf(v.w * sc.w + sh.w, 0.f);
        if (row >= N) { a0 = a1 = a2 = a3 = 0.f; }
        st_h4(Ah + r * LDA + c4, __float2half_rn(a0), __float2half_rn(a1),
              __float2half_rn(a2), __float2half_rn(a3));
    }
    cpasync_wait0();
    __syncthreads();

    const int lane = tid & 31;
    const int w = tid >> 5;
    const int gid = lane >> 2, tig = lane & 3;
    const int wm = w & 3, wn = w >> 2;     // warp tile: rows wm*32.., cols wn*16..

    const int lr = lane & 15;
    const int kh = ((lane >> 4) & 1) << 3;
    unsigned sAh  = (unsigned)__cvta_generic_to_shared(Ah);
    unsigned sBhi = (unsigned)__cvta_generic_to_shared(Bhi);
    unsigned sBlo = (unsigned)__cvta_generic_to_shared(Blo);
    unsigned aAd[2], bHiAd, bLoAd;
    #pragma unroll
    for (int mf = 0; mf < 2; mf++)
        aAd[mf] = sAh + ((wm * 32 + mf * 16 + lr) * LDA + kh) * 2;
    {
        unsigned off = ((wn * 16 + lr) * LDA + kh) * 2;
        bHiAd = sBhi + off; bLoAd = sBlo + off;
    }

    float acc[2][2][4];
    #pragma unroll
    for (int mf = 0; mf < 2; mf++)
        #pragma unroll
        for (int nf = 0; nf < 2; nf++)
            #pragma unroll
            for (int q = 0; q < 4; q++) acc[mf][nf][q] = 0.f;

    #pragma unroll
    for (int kc = 0; kc < 8; kc++) {
        const unsigned kadv = kc * 32;
        unsigned ah[2][4], bh[4], bl[4];
        #pragma unroll
        for (int mf = 0; mf < 2; mf++)
            ldsm4(ah[mf][0], ah[mf][1], ah[mf][2], ah[mf][3], aAd[mf] + kadv);
        ldsm4(bh[0], bh[1], bh[2], bh[3], bHiAd + kadv);
        ldsm4(bl[0], bl[1], bl[2], bl[3], bLoAd + kadv);
        #pragma unroll
        for (int mf = 0; mf < 2; mf++) {
            mma16816h(acc[mf][0], ah[mf], bh[0], bh[2]);
            mma16816h(acc[mf][0], ah[mf], bl[0], bl[2]);
            mma16816h(acc[mf][1], ah[mf], bh[1], bh[3]);
            mma16816h(acc[mf][1], ah[mf], bl[1], bl[3]);
        }
    }

    // ---- epilogue: +b2, store y ----
    const float *b2h = b2 + hd * FOUT;
    #pragma unroll
    for (int nf = 0; nf < 2; nf++) {
        const int col = wn * 16 + nf * 8 + tig * 2;
        const float be = b2h[col], bo = b2h[col + 1];
        #pragma unroll
        for (int mf = 0; mf < 2; mf++) {
            const int r0 = n0 + wm * 32 + mf * 16 + gid;
            const int r1 = r0 + 8;
            if (r0 < N) {
                float2 t; t.x = acc[mf][nf][0] + be; t.y = acc[mf][nf][1] + bo;
                *reinterpret_cast<float2 *>(out + ((size_t)r0 * H + hd) * FOUT + col) = t;
            }
            if (r1 < N) {
                float2 t; t.x = acc[mf][nf][2] + be; t.y = acc[mf][nf][3] + bo;
                *reinterpret_cast<float2 *>(out + ((size_t)r1 * H + hd) * FOUT + col) = t;
            }
        }
    }
}

// ---------------------------------------------------------------------------
extern "C" void kernel_launch(void *const *d_in, const int *in_sizes, int n_in,
                              void *d_out, int out_size)
{
    (void)n_in; (void)out_size;
    const float *x    = (const float *)d_in[0];
    const float *w1   = (const float *)d_in[1];
    const float *b1   = (const float *)d_in[2];
    const float *bn_w = (const float *)d_in[3];
    const float *bn_b = (const float *)d_in[4];
    const float *w2   = (const float *)d_in[5];
    const float *b2   = (const float *)d_in[6];
    float *out = (float *)d_out;

    const int N = in_sizes[0] / (H * FIN);
    const int NT = (N + 127) / 128;

    const int SM1 = 3 * 128 * LDA * 2 + 2 * 4 * HID * 4;                   // 108544 B
    const int SM3 = (128 * LDA + 2 * 64 * LDA) * 2 + 2 * HID * 4;          // 70656 B

    cudaFuncSetAttribute(k_gemm1, cudaFuncAttributeMaxDynamicSharedMemorySize, SM1);
    cudaFuncSetAttribute(k_gemm2, cudaFuncAttributeMaxDynamicSharedMemorySize, SM3);

    k_prep<<<H, 512>>>(w1, w2);
    k_gemm1<<<dim3(NT, H), 512, SM1>>>(x, b1, N, NT);
    k_stats_a<<<dim3(H, NCH), HID>>>(NT);
    k_stats_b<<<H, HID>>>(bn_w, bn_b, N);
    k_gemm2<<<dim3(NT, H), 512, SM3>>>(b2, out, N);
}